// round 6
// baseline (speedup 1.0000x reference)
#include <cuda_runtime.h>
#include <math.h>
#include <float.h>

#define NN       50000
#define EE       800000
#define CENTERSN 1000
#define CAP      128
#define BN_EPS   1e-5f

// ---------------- device scratch (no allocations allowed) ----------------
__device__ __align__(16) float g_xc[CENTERSN * 64];   // relu'd centroid features
__device__ __align__(16) float g_u[NN * 64];          // per-node dst-side contribution (+b_v)
__device__ __align__(16) float g_vw[NN * 64];         // per-node src-side contribution
__device__ __align__(16) float g_mx[NN * 64];         // per-node max of vw over incoming edges
__device__ __align__(16) float g_mn[NN * 64];         // per-node min of vw over incoming edges
__device__ int   g_cursor[NN];                        // in-degree counter / bucket cursor
__device__ int   g_outdeg[NN];                        // out-degree counter
__device__ int   g_bucket[NN * CAP];                  // per-dst src row offsets (src*64)
__device__ float g_sum[64];
__device__ float g_sumsq[64];

// ---------------- K1: centroid grouped-linear + relu, fused with counter init ----------------
__global__ void k_centroid(const float* __restrict__ x_center,
                           const float* __restrict__ W_c,
                           const float* __restrict__ b_c) {
    int idx = blockIdx.x * blockDim.x + threadIdx.x;   // 64000 threads
    if (idx < NN) { g_cursor[idx] = 0; g_outdeg[idx] = 0; }
    if (idx < 64) { g_sum[idx] = 0.f; g_sumsq[idx] = 0.f; }
    int cid = idx >> 6;
    int c   = idx & 63;
    int g   = c >> 4;
    int o   = c & 15;
    float s = b_c[c];
    const float* xr = x_center + cid * 64 + g * 16;
    const float* wr = W_c + g * 256 + o;               // W_c[g, i, o], stride 16 over i
#pragma unroll
    for (int i = 0; i < 16; i++)
        s = fmaf(xr[i], wr[i * 16], s);
    g_xc[idx] = fmaxf(s, 0.f);
}

// ---------------- K2: per-node u / vw precompute (register weights, float4 LDS) ----------------
#define NPB 32
#define XS  68   // padded stride (272B, 16B-aligned rows, conflict-free)
#define FMA4(acc, wbase, v4) \
    acc = fmaf(w[(wbase)+0], (v4).x, acc); acc = fmaf(w[(wbase)+1], (v4).y, acc); \
    acc = fmaf(w[(wbase)+2], (v4).z, acc); acc = fmaf(w[(wbase)+3], (v4).w, acc);
#define FMA4N(accu, accv, wbase, v4) { \
    float w0=w[(wbase)+0], w1=w[(wbase)+1], w2=w[(wbase)+2], w3=w[(wbase)+3]; \
    accu = fmaf(-w0,(v4).x,accu); accu = fmaf(-w1,(v4).y,accu); \
    accu = fmaf(-w2,(v4).z,accu); accu = fmaf(-w3,(v4).w,accu); \
    accv = fmaf( w0,(v4).x,accv); accv = fmaf( w1,(v4).y,accv); \
    accv = fmaf( w2,(v4).z,accv); accv = fmaf( w3,(v4).w,accv); }

__global__ __launch_bounds__(256) void k_nodes(const float* __restrict__ x,
                                               const int*   __restrict__ batch,
                                               const float* __restrict__ Wv,
                                               const float* __restrict__ bv) {
    __shared__ __align__(16) float xs[NPB * XS];
    __shared__ __align__(16) float ys[NPB * XS];
    __shared__ int bs[NPB];

    int tid   = threadIdx.x;
    int node0 = blockIdx.x * NPB;

    if (tid < NPB) {
        int n = node0 + tid;
        bs[tid] = (n < NN) ? batch[n] : 0;
    }
    for (int i = tid; i < NPB * 16; i += 256) {
        int n = i >> 4, kk = i & 15;
        if (node0 + n < NN)
            *(float4*)&xs[n * XS + kk * 4] = __ldg((const float4*)&x[(node0 + n) * 64 + kk * 4]);
    }
    __syncthreads();
    for (int i = tid; i < NPB * 16; i += 256) {
        int n = i >> 4, kk = i & 15;
        *(float4*)&ys[n * XS + kk * 4] = *(const float4*)&g_xc[bs[n] * 64 + kk * 4];
    }

    int o    = tid & 15;
    int slot = (tid >> 4) & 3;
    int g    = tid >> 6;          // warp-uniform group
    int c    = g * 16 + o;

    float w[48];
#pragma unroll
    for (int k = 0; k < 48; k++)
        w[k] = __ldg(&Wv[g * 768 + k * 16 + o]);
    float bvc = __ldg(&bv[c]);
    __syncthreads();

    for (int n = slot; n < NPB; n += 4) {
        if (node0 + n >= NN) break;
        const float* X = &xs[n * XS];
        const float* Y = &ys[n * XS];
        float u = 0.f, v = 0.f;
        if (g == 0) {
#pragma unroll
            for (int kk = 0; kk < 12; kk++) {
                float4 xv = *(const float4*)&X[kk * 4];
                FMA4(u, kk * 4, xv);
            }
        } else if (g == 1) {
#pragma unroll
            for (int kk = 0; kk < 4; kk++) {
                float4 xv = *(const float4*)&X[48 + kk * 4];
                FMA4(u, kk * 4, xv);
            }
#pragma unroll
            for (int kk = 0; kk < 8; kk++) {
                float4 xv = *(const float4*)&X[kk * 4];
                FMA4N(u, v, 16 + kk * 4, xv);
            }
        } else if (g == 2) {
#pragma unroll
            for (int kk = 0; kk < 8; kk++) {
                float4 xv = *(const float4*)&X[32 + kk * 4];
                FMA4N(u, v, kk * 4, xv);
            }
#pragma unroll
            for (int kk = 0; kk < 4; kk++) {
                float4 yv = *(const float4*)&Y[kk * 4];
                FMA4(v, 32 + kk * 4, yv);
            }
        } else {
#pragma unroll
            for (int kk = 0; kk < 12; kk++) {
                float4 yv = *(const float4*)&Y[16 + kk * 4];
                FMA4(v, kk * 4, yv);
            }
        }
        int base = (node0 + n) * 64 + c;
        g_u[base]  = u + bvc;
        g_vw[base] = v;
    }
}

// ---------------- K3: one-pass bucket fill (stores src*64), indeg+outdeg ----------------
__global__ __launch_bounds__(256) void k_bucket(const int* __restrict__ ei) {
    int base = (blockIdx.x * blockDim.x + threadIdx.x) * 4;
    if (base < EE) {                                      // EE % 4 == 0
        int4 d4 = *(const int4*)&ei[EE + base];           // dst quad
        int4 s4 = *(const int4*)&ei[base];                // src quad
        int p0 = atomicAdd(&g_cursor[d4.x], 1);
        int p1 = atomicAdd(&g_cursor[d4.y], 1);
        int p2 = atomicAdd(&g_cursor[d4.z], 1);
        int p3 = atomicAdd(&g_cursor[d4.w], 1);
        atomicAdd(&g_outdeg[s4.x], 1);
        atomicAdd(&g_outdeg[s4.y], 1);
        atomicAdd(&g_outdeg[s4.z], 1);
        atomicAdd(&g_outdeg[s4.w], 1);
        if (p0 < CAP) g_bucket[d4.x * CAP + p0] = s4.x * 64;
        if (p1 < CAP) g_bucket[d4.y * CAP + p1] = s4.y * 64;
        if (p2 < CAP) g_bucket[d4.z * CAP + p2] = s4.z * 64;
        if (p3 < CAP) g_bucket[d4.w * CAP + p3] = s4.w * 64;
    }
}

// ---------------- K4: warp-per-node max/min/vsum + node-level BN stats ----------------
// Per-edge work: fmax, fmin, vsum-add per channel (stats moved to node epilogue)
#define ACCV(v) \
    mx.x = fmaxf(mx.x, (v).x); mx.y = fmaxf(mx.y, (v).y); \
    mx.z = fmaxf(mx.z, (v).z); mx.w = fmaxf(mx.w, (v).w); \
    mn.x = fminf(mn.x, (v).x); mn.y = fminf(mn.y, (v).y); \
    mn.z = fminf(mn.z, (v).z); mn.w = fminf(mn.w, (v).w); \
    vs.x += (v).x; vs.y += (v).y; vs.z += (v).z; vs.w += (v).w;

__global__ __launch_bounds__(256) void k_max() {
    __shared__ float ssum[64], ssq[64];
    int tid = threadIdx.x;
    if (tid < 64) { ssum[tid] = 0.f; ssq[tid] = 0.f; }
    __syncthreads();

    int lane = tid & 31;
    int half = lane >> 4;       // 0: even edges, 1: odd edges
    int l16  = (lane & 15) * 4; // channel base
    int wid  = (blockIdx.x * blockDim.x + tid) >> 5;
    int nw   = (gridDim.x * blockDim.x) >> 5;

    float4 s = make_float4(0.f, 0.f, 0.f, 0.f);
    float4 q = make_float4(0.f, 0.f, 0.f, 0.f);

    for (int node = wid; node < NN; node += nw) {
        int cnt = g_cursor[node];
        int outd = g_outdeg[node];
        if ((cnt | outd) == 0) continue;

        float4 u4  = *(const float4*)&g_u[node * 64 + l16];
        float4 vwi = *(const float4*)&g_vw[node * 64 + l16];
        float4 mx = make_float4(-FLT_MAX, -FLT_MAX, -FLT_MAX, -FLT_MAX);
        float4 mn = make_float4( FLT_MAX,  FLT_MAX,  FLT_MAX,  FLT_MAX);
        float4 vs = make_float4(0.f, 0.f, 0.f, 0.f);

        int m = cnt < CAP ? cnt : CAP;
        const int* bk = &g_bucket[node * CAP];
        int t = half;
        for (; t + 6 < m; t += 8) {       // 4 gathers in flight per half-warp
            int o0 = __ldg(&bk[t]);
            int o1 = __ldg(&bk[t + 2]);
            int o2 = __ldg(&bk[t + 4]);
            int o3 = __ldg(&bk[t + 6]);
            float4 v0 = __ldg((const float4*)&g_vw[o0 + l16]);
            float4 v1 = __ldg((const float4*)&g_vw[o1 + l16]);
            float4 v2 = __ldg((const float4*)&g_vw[o2 + l16]);
            float4 v3 = __ldg((const float4*)&g_vw[o3 + l16]);
            ACCV(v0); ACCV(v1); ACCV(v2); ACCV(v3);
        }
        for (; t + 2 < m; t += 4) {
            int o0 = __ldg(&bk[t]);
            int o1 = __ldg(&bk[t + 2]);
            float4 v0 = __ldg((const float4*)&g_vw[o0 + l16]);
            float4 v1 = __ldg((const float4*)&g_vw[o1 + l16]);
            ACCV(v0); ACCV(v1);
        }
        for (; t < m; t += 2) {
            int o0 = __ldg(&bk[t]);
            float4 v0 = __ldg((const float4*)&g_vw[o0 + l16]);
            ACCV(v0);
        }

        // merge the two half-warps' max/min
        mx.x = fmaxf(mx.x, __shfl_xor_sync(0xffffffffu, mx.x, 16));
        mx.y = fmaxf(mx.y, __shfl_xor_sync(0xffffffffu, mx.y, 16));
        mx.z = fmaxf(mx.z, __shfl_xor_sync(0xffffffffu, mx.z, 16));
        mx.w = fmaxf(mx.w, __shfl_xor_sync(0xffffffffu, mx.w, 16));
        mn.x = fminf(mn.x, __shfl_xor_sync(0xffffffffu, mn.x, 16));
        mn.y = fminf(mn.y, __shfl_xor_sync(0xffffffffu, mn.y, 16));
        mn.z = fminf(mn.z, __shfl_xor_sync(0xffffffffu, mn.z, 16));
        mn.w = fminf(mn.w, __shfl_xor_sync(0xffffffffu, mn.w, 16));

        // stats: q cross term is linear in vsum -> each half adds its own share
        q.x = fmaf(2.f * u4.x, vs.x, q.x);
        q.y = fmaf(2.f * u4.y, vs.y, q.y);
        q.z = fmaf(2.f * u4.z, vs.z, q.z);
        q.w = fmaf(2.f * u4.w, vs.w, q.w);

        if (half == 0) {
            if (cnt > 0) {
                *(float4*)&g_mx[node * 64 + l16] = mx;
                *(float4*)&g_mn[node * 64 + l16] = mn;
            }
            float cf = (float)cnt, of = (float)outd;
            s.x += cf * u4.x + of * vwi.x;
            s.y += cf * u4.y + of * vwi.y;
            s.z += cf * u4.z + of * vwi.z;
            s.w += cf * u4.w + of * vwi.w;
            q.x += cf * u4.x * u4.x + of * vwi.x * vwi.x;
            q.y += cf * u4.y * u4.y + of * vwi.y * vwi.y;
            q.z += cf * u4.z * u4.z + of * vwi.z * vwi.z;
            q.w += cf * u4.w * u4.w + of * vwi.w * vwi.w;
        }
    }
    atomicAdd(&ssum[l16 + 0], s.x);
    atomicAdd(&ssum[l16 + 1], s.y);
    atomicAdd(&ssum[l16 + 2], s.z);
    atomicAdd(&ssum[l16 + 3], s.w);
    atomicAdd(&ssq[l16 + 0], q.x);
    atomicAdd(&ssq[l16 + 1], q.y);
    atomicAdd(&ssq[l16 + 2], q.z);
    atomicAdd(&ssq[l16 + 3], q.w);
    __syncthreads();
    if (tid < 64) {
        atomicAdd(&g_sum[tid],   ssum[tid]);
        atomicAdd(&g_sumsq[tid], ssq[tid]);
    }
}

// ---------------- K5: per-node output, BN affine computed per block ----------------
__global__ __launch_bounds__(256) void k_out(const float* __restrict__ gamma,
                                             const float* __restrict__ beta,
                                             float* __restrict__ out) {
    __shared__ float sc[64], sh[64];
    int tid = threadIdx.x;
    if (tid < 64) {
        float invE = 1.f / (float)EE;
        float mu  = g_sum[tid] * invE;
        float var = fmaxf(g_sumsq[tid] * invE - mu * mu, 0.f);
        float a   = gamma[tid] * rsqrtf(var + BN_EPS);
        sc[tid] = a;
        sh[tid] = beta[tid] - a * mu;
    }
    __syncthreads();

    int idx  = blockIdx.x * blockDim.x + tid;   // NN*16 threads
    int node = idx >> 4;
    int c4   = idx & 15;
    int deg  = g_cursor[node];
    float4 r = make_float4(0.f, 0.f, 0.f, 0.f);
    if (deg > 0) {
        float4 a  = *(const float4*)&sc[c4 * 4];
        float4 b  = *(const float4*)&sh[c4 * 4];
        float4 u  = *(const float4*)&g_u[node * 64 + c4 * 4];
        float4 mx = *(const float4*)&g_mx[node * 64 + c4 * 4];
        float4 mn = *(const float4*)&g_mn[node * 64 + c4 * 4];
        float m0 = (a.x >= 0.f) ? mx.x : mn.x;
        float m1 = (a.y >= 0.f) ? mx.y : mn.y;
        float m2 = (a.z >= 0.f) ? mx.z : mn.z;
        float m3 = (a.w >= 0.f) ? mx.w : mn.w;
        r.x = fmaxf(fmaf(a.x, u.x + m0, b.x), 0.f);
        r.y = fmaxf(fmaf(a.y, u.y + m1, b.y), 0.f);
        r.z = fmaxf(fmaf(a.z, u.z + m2, b.z), 0.f);
        r.w = fmaxf(fmaf(a.w, u.w + m3, b.w), 0.f);
    }
    *(float4*)&out[node * 64 + c4 * 4] = r;
}

// ---------------- launch ----------------
extern "C" void kernel_launch(void* const* d_in, const int* in_sizes, int n_in,
                              void* d_out, int out_size) {
    const float* x        = (const float*)d_in[0];
    const int*   batch    = (const int*)  d_in[1];
    const int*   ei       = (const int*)  d_in[2];
    const float* x_center = (const float*)d_in[3];
    // d_in[4] = batch_center (unused by reference)
    const float* W_c      = (const float*)d_in[5];
    const float* b_c      = (const float*)d_in[6];
    const float* W_v      = (const float*)d_in[7];
    const float* b_v      = (const float*)d_in[8];
    const float* gamma    = (const float*)d_in[9];
    const float* beta     = (const float*)d_in[10];
    float* out = (float*)d_out;

    k_centroid<<<250, 256>>>(x_center, W_c, b_c);      // also zeroes counters
    k_nodes   <<<(NN + NPB - 1) / NPB, 256>>>(x, batch, W_v, b_v);
    k_bucket  <<<(EE / 4 + 255) / 256, 256>>>(ei);
    k_max     <<<2000, 256>>>();
    k_out     <<<NN * 16 / 256, 256>>>(gamma, beta, out);
}

// round 7
// speedup vs baseline: 1.0976x; 1.0976x over previous
#include <cuda_runtime.h>
#include <math.h>
#include <float.h>

#define NN       50000
#define EE       800000
#define CENTERSN 1000
#define CAP      128
#define BN_EPS   1e-5f

// ---------------- device scratch (no allocations allowed) ----------------
__device__ __align__(16) float g_xc[CENTERSN * 64];   // relu'd centroid features
__device__ __align__(16) float g_u[NN * 64];          // per-node dst-side contribution (+b_v)
__device__ __align__(16) float g_vw[NN * 64];         // per-node src-side contribution
__device__ __align__(16) float g_mx[NN * 64];         // per-node max of vw over incoming edges
__device__ __align__(16) float g_mn[NN * 64];         // per-node min of vw over incoming edges
__device__ int   g_cursor[NN];                        // in-degree counter / bucket cursor
__device__ int   g_outdeg[NN];                        // out-degree counter
__device__ __align__(16) int g_bucket[NN * CAP];      // per-dst src row offsets (src*64)
__device__ float g_sum[64];
__device__ float g_sumsq[64];

// ---------------- K1: centroid grouped-linear + relu, fused with counter init ----------------
__global__ void k_centroid(const float* __restrict__ x_center,
                           const float* __restrict__ W_c,
                           const float* __restrict__ b_c) {
    int idx = blockIdx.x * blockDim.x + threadIdx.x;   // 64000 threads
    if (idx < NN) { g_cursor[idx] = 0; g_outdeg[idx] = 0; }
    if (idx < 64) { g_sum[idx] = 0.f; g_sumsq[idx] = 0.f; }
    int cid = idx >> 6;
    int c   = idx & 63;
    int g   = c >> 4;
    int o   = c & 15;
    float s = b_c[c];
    const float* xr = x_center + cid * 64 + g * 16;
    const float* wr = W_c + g * 256 + o;               // W_c[g, i, o], stride 16 over i
#pragma unroll
    for (int i = 0; i < 16; i++)
        s = fmaf(xr[i], wr[i * 16], s);
    g_xc[idx] = fmaxf(s, 0.f);
}

// ---------------- K2: per-node u / vw precompute (register weights, float4 LDS) ----------------
#define NPB 32
#define XS  68   // padded stride (272B, 16B-aligned rows, conflict-free)
#define FMA4(acc, wbase, v4) \
    acc = fmaf(w[(wbase)+0], (v4).x, acc); acc = fmaf(w[(wbase)+1], (v4).y, acc); \
    acc = fmaf(w[(wbase)+2], (v4).z, acc); acc = fmaf(w[(wbase)+3], (v4).w, acc);
#define FMA4N(accu, accv, wbase, v4) { \
    float w0=w[(wbase)+0], w1=w[(wbase)+1], w2=w[(wbase)+2], w3=w[(wbase)+3]; \
    accu = fmaf(-w0,(v4).x,accu); accu = fmaf(-w1,(v4).y,accu); \
    accu = fmaf(-w2,(v4).z,accu); accu = fmaf(-w3,(v4).w,accu); \
    accv = fmaf( w0,(v4).x,accv); accv = fmaf( w1,(v4).y,accv); \
    accv = fmaf( w2,(v4).z,accv); accv = fmaf( w3,(v4).w,accv); }

__global__ __launch_bounds__(256) void k_nodes(const float* __restrict__ x,
                                               const int*   __restrict__ batch,
                                               const float* __restrict__ Wv,
                                               const float* __restrict__ bv) {
    __shared__ __align__(16) float xs[NPB * XS];
    __shared__ __align__(16) float ys[NPB * XS];
    __shared__ int bs[NPB];

    int tid   = threadIdx.x;
    int node0 = blockIdx.x * NPB;

    if (tid < NPB) {
        int n = node0 + tid;
        bs[tid] = (n < NN) ? batch[n] : 0;
    }
    for (int i = tid; i < NPB * 16; i += 256) {
        int n = i >> 4, kk = i & 15;
        if (node0 + n < NN)
            *(float4*)&xs[n * XS + kk * 4] = __ldg((const float4*)&x[(node0 + n) * 64 + kk * 4]);
    }
    __syncthreads();
    for (int i = tid; i < NPB * 16; i += 256) {
        int n = i >> 4, kk = i & 15;
        *(float4*)&ys[n * XS + kk * 4] = *(const float4*)&g_xc[bs[n] * 64 + kk * 4];
    }

    int o    = tid & 15;
    int slot = (tid >> 4) & 3;
    int g    = tid >> 6;          // warp-uniform group
    int c    = g * 16 + o;

    float w[48];
#pragma unroll
    for (int k = 0; k < 48; k++)
        w[k] = __ldg(&Wv[g * 768 + k * 16 + o]);
    float bvc = __ldg(&bv[c]);
    __syncthreads();

    for (int n = slot; n < NPB; n += 4) {
        if (node0 + n >= NN) break;
        const float* X = &xs[n * XS];
        const float* Y = &ys[n * XS];
        float u = 0.f, v = 0.f;
        if (g == 0) {
#pragma unroll
            for (int kk = 0; kk < 12; kk++) {
                float4 xv = *(const float4*)&X[kk * 4];
                FMA4(u, kk * 4, xv);
            }
        } else if (g == 1) {
#pragma unroll
            for (int kk = 0; kk < 4; kk++) {
                float4 xv = *(const float4*)&X[48 + kk * 4];
                FMA4(u, kk * 4, xv);
            }
#pragma unroll
            for (int kk = 0; kk < 8; kk++) {
                float4 xv = *(const float4*)&X[kk * 4];
                FMA4N(u, v, 16 + kk * 4, xv);
            }
        } else if (g == 2) {
#pragma unroll
            for (int kk = 0; kk < 8; kk++) {
                float4 xv = *(const float4*)&X[32 + kk * 4];
                FMA4N(u, v, kk * 4, xv);
            }
#pragma unroll
            for (int kk = 0; kk < 4; kk++) {
                float4 yv = *(const float4*)&Y[kk * 4];
                FMA4(v, 32 + kk * 4, yv);
            }
        } else {
#pragma unroll
            for (int kk = 0; kk < 12; kk++) {
                float4 yv = *(const float4*)&Y[16 + kk * 4];
                FMA4(v, kk * 4, yv);
            }
        }
        int base = (node0 + n) * 64 + c;
        g_u[base]  = u + bvc;
        g_vw[base] = v;
    }
}

// ---------------- K3: one-pass bucket fill (stores src*64), indeg+outdeg ----------------
__global__ __launch_bounds__(256) void k_bucket(const int* __restrict__ ei) {
    int base = (blockIdx.x * blockDim.x + threadIdx.x) * 4;
    if (base < EE) {                                      // EE % 4 == 0
        int4 d4 = *(const int4*)&ei[EE + base];           // dst quad
        int4 s4 = *(const int4*)&ei[base];                // src quad
        int p0 = atomicAdd(&g_cursor[d4.x], 1);
        int p1 = atomicAdd(&g_cursor[d4.y], 1);
        int p2 = atomicAdd(&g_cursor[d4.z], 1);
        int p3 = atomicAdd(&g_cursor[d4.w], 1);
        atomicAdd(&g_outdeg[s4.x], 1);
        atomicAdd(&g_outdeg[s4.y], 1);
        atomicAdd(&g_outdeg[s4.z], 1);
        atomicAdd(&g_outdeg[s4.w], 1);
        if (p0 < CAP) g_bucket[d4.x * CAP + p0] = s4.x * 64;
        if (p1 < CAP) g_bucket[d4.y * CAP + p1] = s4.y * 64;
        if (p2 < CAP) g_bucket[d4.z * CAP + p2] = s4.z * 64;
        if (p3 < CAP) g_bucket[d4.w * CAP + p3] = s4.w * 64;
    }
}

// ---------------- K4: warp-per-node, float2/lane, max/min/vsum + node-level BN stats ----------------
// Minimal live state across the gather loop: mx, mn, vs (3 x float2).
#define ACC2(v) \
    mx.x = fmaxf(mx.x, (v).x); mx.y = fmaxf(mx.y, (v).y); \
    mn.x = fminf(mn.x, (v).x); mn.y = fminf(mn.y, (v).y); \
    vs.x += (v).x; vs.y += (v).y;

__global__ __launch_bounds__(256) void k_max() {
    __shared__ float ssum[64], ssq[64];
    int tid = threadIdx.x;
    if (tid < 64) { ssum[tid] = 0.f; ssq[tid] = 0.f; }
    __syncthreads();

    int lane = tid & 31;
    int c2   = lane * 2;                        // this lane's channel pair
    int wid  = (blockIdx.x * blockDim.x + tid) >> 5;
    int nw   = (gridDim.x * blockDim.x) >> 5;

    float2 s = make_float2(0.f, 0.f);
    float2 q = make_float2(0.f, 0.f);

    for (int node = wid; node < NN; node += nw) {
        int cnt  = g_cursor[node];
        int outd = g_outdeg[node];
        if ((cnt | outd) == 0) continue;

        float2 mx = make_float2(-FLT_MAX, -FLT_MAX);
        float2 mn = make_float2( FLT_MAX,  FLT_MAX);
        float2 vs = make_float2(0.f, 0.f);

        int m = cnt < CAP ? cnt : CAP;
        const int* bk = &g_bucket[node * CAP];
        int t = 0;
        for (; t + 4 <= m; t += 4) {            // 1 broadcast int4 + 4 row gathers in flight
            int4 o4 = __ldg((const int4*)&bk[t]);
            float2 v0 = __ldg((const float2*)&g_vw[o4.x + c2]);
            float2 v1 = __ldg((const float2*)&g_vw[o4.y + c2]);
            float2 v2 = __ldg((const float2*)&g_vw[o4.z + c2]);
            float2 v3 = __ldg((const float2*)&g_vw[o4.w + c2]);
            ACC2(v0); ACC2(v1); ACC2(v2); ACC2(v3);
        }
        for (; t < m; t++) {
            int o = __ldg(&bk[t]);
            float2 v = __ldg((const float2*)&g_vw[o + c2]);
            ACC2(v);
        }

        // node epilogue: store extrema, accumulate separable BN stats
        int rb = node * 64 + c2;
        if (cnt > 0) {
            *(float2*)&g_mx[rb] = mx;
            *(float2*)&g_mn[rb] = mn;
        }
        float2 u  = *(const float2*)&g_u[rb];
        float2 vw = *(const float2*)&g_vw[rb];
        float cf = (float)cnt, of = (float)outd;
        s.x += cf * u.x + of * vw.x;
        s.y += cf * u.y + of * vw.y;
        q.x += 2.f * u.x * vs.x + cf * u.x * u.x + of * vw.x * vw.x;
        q.y += 2.f * u.y * vs.y + cf * u.y * u.y + of * vw.y * vw.y;
    }
    atomicAdd(&ssum[c2 + 0], s.x);
    atomicAdd(&ssum[c2 + 1], s.y);
    atomicAdd(&ssq[c2 + 0], q.x);
    atomicAdd(&ssq[c2 + 1], q.y);
    __syncthreads();
    if (tid < 64) {
        atomicAdd(&g_sum[tid],   ssum[tid]);
        atomicAdd(&g_sumsq[tid], ssq[tid]);
    }
}

// ---------------- K5: per-node output, BN affine computed per block ----------------
__global__ __launch_bounds__(256) void k_out(const float* __restrict__ gamma,
                                             const float* __restrict__ beta,
                                             float* __restrict__ out) {
    __shared__ float sc[64], sh[64];
    int tid = threadIdx.x;
    if (tid < 64) {
        float invE = 1.f / (float)EE;
        float mu  = g_sum[tid] * invE;
        float var = fmaxf(g_sumsq[tid] * invE - mu * mu, 0.f);
        float a   = gamma[tid] * rsqrtf(var + BN_EPS);
        sc[tid] = a;
        sh[tid] = beta[tid] - a * mu;
    }
    __syncthreads();

    int idx  = blockIdx.x * blockDim.x + tid;   // NN*16 threads
    int node = idx >> 4;
    int c4   = idx & 15;
    int deg  = g_cursor[node];
    float4 r = make_float4(0.f, 0.f, 0.f, 0.f);
    if (deg > 0) {
        float4 a  = *(const float4*)&sc[c4 * 4];
        float4 b  = *(const float4*)&sh[c4 * 4];
        float4 u  = *(const float4*)&g_u[node * 64 + c4 * 4];
        float4 mx = *(const float4*)&g_mx[node * 64 + c4 * 4];
        float4 mn = *(const float4*)&g_mn[node * 64 + c4 * 4];
        float m0 = (a.x >= 0.f) ? mx.x : mn.x;
        float m1 = (a.y >= 0.f) ? mx.y : mn.y;
        float m2 = (a.z >= 0.f) ? mx.z : mn.z;
        float m3 = (a.w >= 0.f) ? mx.w : mn.w;
        r.x = fmaxf(fmaf(a.x, u.x + m0, b.x), 0.f);
        r.y = fmaxf(fmaf(a.y, u.y + m1, b.y), 0.f);
        r.z = fmaxf(fmaf(a.z, u.z + m2, b.z), 0.f);
        r.w = fmaxf(fmaf(a.w, u.w + m3, b.w), 0.f);
    }
    *(float4*)&out[node * 64 + c4 * 4] = r;
}

// ---------------- launch ----------------
extern "C" void kernel_launch(void* const* d_in, const int* in_sizes, int n_in,
                              void* d_out, int out_size) {
    const float* x        = (const float*)d_in[0];
    const int*   batch    = (const int*)  d_in[1];
    const int*   ei       = (const int*)  d_in[2];
    const float* x_center = (const float*)d_in[3];
    // d_in[4] = batch_center (unused by reference)
    const float* W_c      = (const float*)d_in[5];
    const float* b_c      = (const float*)d_in[6];
    const float* W_v      = (const float*)d_in[7];
    const float* b_v      = (const float*)d_in[8];
    const float* gamma    = (const float*)d_in[9];
    const float* beta     = (const float*)d_in[10];
    float* out = (float*)d_out;

    k_centroid<<<250, 256>>>(x_center, W_c, b_c);      // also zeroes counters
    k_nodes   <<<(NN + NPB - 1) / NPB, 256>>>(x, batch, W_v, b_v);
    k_bucket  <<<(EE / 4 + 255) / 256, 256>>>(ei);
    k_max     <<<2000, 256>>>();
    k_out     <<<NN * 16 / 256, 256>>>(gamma, beta, out);
}

// round 8
// speedup vs baseline: 1.3638x; 1.2425x over previous
#include <cuda_runtime.h>
#include <math.h>
#include <float.h>

#define NN       50000
#define EE       800000
#define CENTERSN 1000
#define CAP      128
#define BN_EPS   1e-5f

// ---------------- device scratch (no allocations allowed) ----------------
__device__ __align__(16) float g_xc[CENTERSN * 64];   // relu'd centroid features
__device__ __align__(16) float g_u[NN * 64];          // SIGNED per-node dst contribution (s_c*(u+b_v))
__device__ __align__(16) float g_vw[NN * 64];         // SIGNED per-node src contribution (s_c*vw)
__device__ __align__(16) float g_mx[NN * 64];         // per-node max of signed vw over incoming edges
__device__ int   g_cursor[NN];                        // in-degree counter / bucket cursor
__device__ int   g_outdeg[NN];                        // out-degree counter
__device__ __align__(16) int g_bucket[NN * CAP];      // per-dst src row BYTE offsets (src*256)
__device__ float g_sum[64];                           // signed Σh'
__device__ float g_sumsq[64];                         // Σh² (sign-free)

// ---------------- K1: centroid grouped-linear + relu, fused with counter init ----------------
__global__ void k_centroid(const float* __restrict__ x_center,
                           const float* __restrict__ W_c,
                           const float* __restrict__ b_c) {
    int idx = blockIdx.x * blockDim.x + threadIdx.x;   // 64000 threads
    if (idx < NN) { g_cursor[idx] = 0; g_outdeg[idx] = 0; }
    if (idx < 64) { g_sum[idx] = 0.f; g_sumsq[idx] = 0.f; }
    int cid = idx >> 6;
    int c   = idx & 63;
    int g   = c >> 4;
    int o   = c & 15;
    float s = b_c[c];
    const float* xr = x_center + cid * 64 + g * 16;
    const float* wr = W_c + g * 256 + o;               // W_c[g, i, o], stride 16 over i
#pragma unroll
    for (int i = 0; i < 16; i++)
        s = fmaf(xr[i], wr[i * 16], s);
    g_xc[idx] = fmaxf(s, 0.f);
}

// ---------------- K2: per-node u/vw precompute + FUSED edge bucketing ----------------
// Channel c = 16g+o reads m rows [48g, 48g+48); m = [x_i ; x_j - x_i ; y_j]
// Outputs are sign-folded by s_c = sign(gamma_c) so k_max only needs a max.
#define NPB 32
#define XS  68   // padded stride (272B, 16B-aligned rows, conflict-free)
#define FMA4(acc, wbase, v4) \
    acc = fmaf(w[(wbase)+0], (v4).x, acc); acc = fmaf(w[(wbase)+1], (v4).y, acc); \
    acc = fmaf(w[(wbase)+2], (v4).z, acc); acc = fmaf(w[(wbase)+3], (v4).w, acc);
#define FMA4N(accu, accv, wbase, v4) { \
    float w0=w[(wbase)+0], w1=w[(wbase)+1], w2=w[(wbase)+2], w3=w[(wbase)+3]; \
    accu = fmaf(-w0,(v4).x,accu); accu = fmaf(-w1,(v4).y,accu); \
    accu = fmaf(-w2,(v4).z,accu); accu = fmaf(-w3,(v4).w,accu); \
    accv = fmaf( w0,(v4).x,accv); accv = fmaf( w1,(v4).y,accv); \
    accv = fmaf( w2,(v4).z,accv); accv = fmaf( w3,(v4).w,accv); }

__global__ __launch_bounds__(256) void k_nodes(const float* __restrict__ x,
                                               const int*   __restrict__ batch,
                                               const float* __restrict__ Wv,
                                               const float* __restrict__ bv,
                                               const float* __restrict__ gamma,
                                               const int*   __restrict__ ei) {
    __shared__ __align__(16) float xs[NPB * XS];
    __shared__ __align__(16) float ys[NPB * XS];
    __shared__ int bs[NPB];

    int tid   = threadIdx.x;
    int node0 = blockIdx.x * NPB;

    // ---- fused edge bucketing: one edge PAIR per thread (latency hides under GEMM) ----
    {
        int ebase = (blockIdx.x * 256 + tid) * 2;
        if (ebase < EE) {                                  // EE even
            int2 s2 = *(const int2*)&ei[ebase];            // src pair
            int2 d2 = *(const int2*)&ei[EE + ebase];       // dst pair
            int p0 = atomicAdd(&g_cursor[d2.x], 1);
            int p1 = atomicAdd(&g_cursor[d2.y], 1);
            atomicAdd(&g_outdeg[s2.x], 1);
            atomicAdd(&g_outdeg[s2.y], 1);
            if (p0 < CAP) g_bucket[d2.x * CAP + p0] = s2.x * 256;   // byte offset
            if (p1 < CAP) g_bucket[d2.y * CAP + p1] = s2.y * 256;
        }
    }

    if (tid < NPB) {
        int n = node0 + tid;
        bs[tid] = (n < NN) ? batch[n] : 0;
    }
    for (int i = tid; i < NPB * 16; i += 256) {
        int n = i >> 4, kk = i & 15;
        if (node0 + n < NN)
            *(float4*)&xs[n * XS + kk * 4] = __ldg((const float4*)&x[(node0 + n) * 64 + kk * 4]);
    }
    __syncthreads();
    for (int i = tid; i < NPB * 16; i += 256) {
        int n = i >> 4, kk = i & 15;
        *(float4*)&ys[n * XS + kk * 4] = *(const float4*)&g_xc[bs[n] * 64 + kk * 4];
    }

    int o    = tid & 15;
    int slot = (tid >> 4) & 3;
    int g    = tid >> 6;          // warp-uniform group
    int c    = g * 16 + o;

    float w[48];
#pragma unroll
    for (int k = 0; k < 48; k++)
        w[k] = __ldg(&Wv[g * 768 + k * 16 + o]);
    float bvc = __ldg(&bv[c]);
    float sgn = (__ldg(&gamma[c]) >= 0.f) ? 1.f : -1.f;   // sign fold
    __syncthreads();

    for (int n = slot; n < NPB; n += 4) {
        if (node0 + n >= NN) break;
        const float* X = &xs[n * XS];
        const float* Y = &ys[n * XS];
        float u = 0.f, v = 0.f;
        if (g == 0) {
#pragma unroll
            for (int kk = 0; kk < 12; kk++) {
                float4 xv = *(const float4*)&X[kk * 4];
                FMA4(u, kk * 4, xv);
            }
        } else if (g == 1) {
#pragma unroll
            for (int kk = 0; kk < 4; kk++) {
                float4 xv = *(const float4*)&X[48 + kk * 4];
                FMA4(u, kk * 4, xv);
            }
#pragma unroll
            for (int kk = 0; kk < 8; kk++) {
                float4 xv = *(const float4*)&X[kk * 4];
                FMA4N(u, v, 16 + kk * 4, xv);
            }
        } else if (g == 2) {
#pragma unroll
            for (int kk = 0; kk < 8; kk++) {
                float4 xv = *(const float4*)&X[32 + kk * 4];
                FMA4N(u, v, kk * 4, xv);
            }
#pragma unroll
            for (int kk = 0; kk < 4; kk++) {
                float4 yv = *(const float4*)&Y[kk * 4];
                FMA4(v, 32 + kk * 4, yv);
            }
        } else {
#pragma unroll
            for (int kk = 0; kk < 12; kk++) {
                float4 yv = *(const float4*)&Y[16 + kk * 4];
                FMA4(v, kk * 4, yv);
            }
        }
        int base = (node0 + n) * 64 + c;
        g_u[base]  = sgn * (u + bvc);
        g_vw[base] = sgn * v;
    }
}

// ---------------- K3: warp-per-node signed-max + vsum + node-level BN stats ----------------
// Per-edge work: fmax + add per channel only (4 warp math instrs/edge).
#define ACC2(v) \
    mx.x = fmaxf(mx.x, (v).x); mx.y = fmaxf(mx.y, (v).y); \
    vs.x += (v).x; vs.y += (v).y;

__global__ __launch_bounds__(256) void k_max() {
    __shared__ float ssum[64], ssq[64];
    int tid = threadIdx.x;
    if (tid < 64) { ssum[tid] = 0.f; ssq[tid] = 0.f; }
    __syncthreads();

    int lane = tid & 31;
    int c2   = lane * 2;                        // this lane's channel pair
    const char* vwb = (const char*)g_vw + lane * 8;   // per-lane gather base
    int wid  = (blockIdx.x * blockDim.x + tid) >> 5;
    int nw   = (gridDim.x * blockDim.x) >> 5;

    float2 s = make_float2(0.f, 0.f);
    float2 q = make_float2(0.f, 0.f);

    for (int node = wid; node < NN; node += nw) {
        int cnt  = g_cursor[node];
        int outd = g_outdeg[node];
        if ((cnt | outd) == 0) continue;

        float2 mx = make_float2(-FLT_MAX, -FLT_MAX);
        float2 vs = make_float2(0.f, 0.f);

        int m = cnt < CAP ? cnt : CAP;
        const int* bk = &g_bucket[node * CAP];
        int t = 0;
        for (; t + 4 <= m; t += 4) {            // 1 broadcast int4 + 4 row gathers in flight
            int4 o4 = __ldg((const int4*)&bk[t]);
            float2 v0 = __ldg((const float2*)(vwb + o4.x));
            float2 v1 = __ldg((const float2*)(vwb + o4.y));
            float2 v2 = __ldg((const float2*)(vwb + o4.z));
            float2 v3 = __ldg((const float2*)(vwb + o4.w));
            ACC2(v0); ACC2(v1); ACC2(v2); ACC2(v3);
        }
        for (; t < m; t++) {
            int o = __ldg(&bk[t]);
            float2 v = __ldg((const float2*)(vwb + o));
            ACC2(v);
        }

        // node epilogue: store extremum, accumulate separable BN stats
        int rb = node * 64 + c2;
        if (cnt > 0)
            *(float2*)&g_mx[rb] = mx;
        float2 u  = *(const float2*)&g_u[rb];
        float2 vw = *(const float2*)&g_vw[rb];
        float cf = (float)cnt, of = (float)outd;
        s.x += cf * u.x + of * vw.x;
        s.y += cf * u.y + of * vw.y;
        q.x += 2.f * u.x * vs.x + cf * u.x * u.x + of * vw.x * vw.x;
        q.y += 2.f * u.y * vs.y + cf * u.y * u.y + of * vw.y * vw.y;
    }
    atomicAdd(&ssum[c2 + 0], s.x);
    atomicAdd(&ssum[c2 + 1], s.y);
    atomicAdd(&ssq[c2 + 0], q.x);
    atomicAdd(&ssq[c2 + 1], q.y);
    __syncthreads();
    if (tid < 64) {
        atomicAdd(&g_sum[tid],   ssum[tid]);
        atomicAdd(&g_sumsq[tid], ssq[tid]);
    }
}

// ---------------- K4: per-node output, BN affine computed per block (sign-aware) ----------------
__global__ __launch_bounds__(256) void k_out(const float* __restrict__ gamma,
                                             const float* __restrict__ beta,
                                             float* __restrict__ out) {
    __shared__ float sc[64], sh[64];
    int tid = threadIdx.x;
    if (tid < 64) {
        float gm  = gamma[tid];
        float sg  = (gm >= 0.f) ? 1.f : -1.f;
        float invE = 1.f / (float)EE;
        float mu  = sg * g_sum[tid] * invE;                 // un-sign the mean
        float var = fmaxf(g_sumsq[tid] * invE - mu * mu, 0.f);
        float a   = gm * rsqrtf(var + BN_EPS);
        sc[tid] = a * sg;                                   // a' = |gamma|*rsqrt  (acts on signed u'+mx')
        sh[tid] = beta[tid] - a * mu;
    }
    __syncthreads();

    int idx  = blockIdx.x * blockDim.x + tid;   // NN*16 threads
    int node = idx >> 4;
    int c4   = idx & 15;
    int deg  = g_cursor[node];
    float4 r = make_float4(0.f, 0.f, 0.f, 0.f);
    if (deg > 0) {
        float4 a  = *(const float4*)&sc[c4 * 4];
        float4 b  = *(const float4*)&sh[c4 * 4];
        float4 u  = *(const float4*)&g_u[node * 64 + c4 * 4];
        float4 mx = *(const float4*)&g_mx[node * 64 + c4 * 4];
        r.x = fmaxf(fmaf(a.x, u.x + mx.x, b.x), 0.f);
        r.y = fmaxf(fmaf(a.y, u.y + mx.y, b.y), 0.f);
        r.z = fmaxf(fmaf(a.z, u.z + mx.z, b.z), 0.f);
        r.w = fmaxf(fmaf(a.w, u.w + mx.w, b.w), 0.f);
    }
    *(float4*)&out[node * 64 + c4 * 4] = r;
}

// ---------------- launch ----------------
extern "C" void kernel_launch(void* const* d_in, const int* in_sizes, int n_in,
                              void* d_out, int out_size) {
    const float* x        = (const float*)d_in[0];
    const int*   batch    = (const int*)  d_in[1];
    const int*   ei       = (const int*)  d_in[2];
    const float* x_center = (const float*)d_in[3];
    // d_in[4] = batch_center (unused by reference)
    const float* W_c      = (const float*)d_in[5];
    const float* b_c      = (const float*)d_in[6];
    const float* W_v      = (const float*)d_in[7];
    const float* b_v      = (const float*)d_in[8];
    const float* gamma    = (const float*)d_in[9];
    const float* beta     = (const float*)d_in[10];
    float* out = (float*)d_out;

    k_centroid<<<250, 256>>>(x_center, W_c, b_c);              // also zeroes counters
    k_nodes   <<<(NN + NPB - 1) / NPB, 256>>>(x, batch, W_v, b_v, gamma, ei);  // + fused bucketing
    k_max     <<<2000, 256>>>();
    k_out     <<<NN * 16 / 256, 256>>>(gamma, beta, out);
}

// round 9
// speedup vs baseline: 1.4064x; 1.0313x over previous
#include <cuda_runtime.h>
#include <math.h>
#include <float.h>

#define NN       50000
#define EE       800000
#define CENTERSN 1000
#define CAP      128
#define BN_EPS   1e-5f

// ---------------- device scratch (no allocations allowed) ----------------
__device__ __align__(16) float g_xc[CENTERSN * 64];   // relu'd centroid features
__device__ __align__(16) float g_u[NN * 64];          // SIGNED per-node dst contribution (s_c*(u+b_v))
__device__ __align__(16) float g_vw[NN * 64];         // SIGNED per-node src contribution (s_c*vw)
__device__ __align__(16) float g_mx[NN * 64];         // u' + max(vw') over incoming edges (fused)
__device__ int   g_cursor[NN];                        // in-degree counter / bucket cursor
__device__ int   g_outdeg[NN];                        // out-degree counter
__device__ __align__(16) int g_bucket[NN * CAP];      // per-dst src row BYTE offsets (src*256)
__device__ float g_sum[64];                           // signed Σh'
__device__ float g_sumsq[64];                         // Σh² (sign-free)

// ---------------- K1: centroid grouped-linear + relu, fused with counter init ----------------
__global__ void k_centroid(const float* __restrict__ x_center,
                           const float* __restrict__ W_c,
                           const float* __restrict__ b_c) {
    int idx = blockIdx.x * blockDim.x + threadIdx.x;   // 64000 threads
    if (idx < NN) { g_cursor[idx] = 0; g_outdeg[idx] = 0; }
    if (idx < 64) { g_sum[idx] = 0.f; g_sumsq[idx] = 0.f; }
    int cid = idx >> 6;
    int c   = idx & 63;
    int g   = c >> 4;
    int o   = c & 15;
    float s = b_c[c];
    const float* xr = x_center + cid * 64 + g * 16;
    const float* wr = W_c + g * 256 + o;               // W_c[g, i, o], stride 16 over i
#pragma unroll
    for (int i = 0; i < 16; i++)
        s = fmaf(xr[i], wr[i * 16], s);
    g_xc[idx] = fmaxf(s, 0.f);
}

// ---------------- K2: per-node u/vw precompute + FUSED edge bucketing ----------------
// Channel c = 16g+o reads m rows [48g, 48g+48); m = [x_i ; x_j - x_i ; y_j]
// Outputs are sign-folded by s_c = sign(gamma_c) so k_max only needs a max.
#define NPB 32
#define XS  68   // padded stride (272B, 16B-aligned rows, conflict-free)
#define FMA4(acc, wbase, v4) \
    acc = fmaf(w[(wbase)+0], (v4).x, acc); acc = fmaf(w[(wbase)+1], (v4).y, acc); \
    acc = fmaf(w[(wbase)+2], (v4).z, acc); acc = fmaf(w[(wbase)+3], (v4).w, acc);
#define FMA4N(accu, accv, wbase, v4) { \
    float w0=w[(wbase)+0], w1=w[(wbase)+1], w2=w[(wbase)+2], w3=w[(wbase)+3]; \
    accu = fmaf(-w0,(v4).x,accu); accu = fmaf(-w1,(v4).y,accu); \
    accu = fmaf(-w2,(v4).z,accu); accu = fmaf(-w3,(v4).w,accu); \
    accv = fmaf( w0,(v4).x,accv); accv = fmaf( w1,(v4).y,accv); \
    accv = fmaf( w2,(v4).z,accv); accv = fmaf( w3,(v4).w,accv); }

__global__ __launch_bounds__(256) void k_nodes(const float* __restrict__ x,
                                               const int*   __restrict__ batch,
                                               const float* __restrict__ Wv,
                                               const float* __restrict__ bv,
                                               const float* __restrict__ gamma,
                                               const int*   __restrict__ ei) {
    __shared__ __align__(16) float xs[NPB * XS];
    __shared__ __align__(16) float ys[NPB * XS];
    __shared__ int bs[NPB];

    int tid   = threadIdx.x;
    int node0 = blockIdx.x * NPB;

    // ---- fused edge bucketing: one edge PAIR per thread (latency hides under GEMM) ----
    {
        int ebase = (blockIdx.x * 256 + tid) * 2;
        if (ebase < EE) {                                  // EE even
            int2 s2 = *(const int2*)&ei[ebase];            // src pair
            int2 d2 = *(const int2*)&ei[EE + ebase];       // dst pair
            int p0 = atomicAdd(&g_cursor[d2.x], 1);
            int p1 = atomicAdd(&g_cursor[d2.y], 1);
            atomicAdd(&g_outdeg[s2.x], 1);
            atomicAdd(&g_outdeg[s2.y], 1);
            if (p0 < CAP) g_bucket[d2.x * CAP + p0] = s2.x * 256;   // byte offset
            if (p1 < CAP) g_bucket[d2.y * CAP + p1] = s2.y * 256;
        }
    }

    if (tid < NPB) {
        int n = node0 + tid;
        bs[tid] = (n < NN) ? batch[n] : 0;
    }
    for (int i = tid; i < NPB * 16; i += 256) {
        int n = i >> 4, kk = i & 15;
        if (node0 + n < NN)
            *(float4*)&xs[n * XS + kk * 4] = __ldg((const float4*)&x[(node0 + n) * 64 + kk * 4]);
    }
    __syncthreads();
    for (int i = tid; i < NPB * 16; i += 256) {
        int n = i >> 4, kk = i & 15;
        *(float4*)&ys[n * XS + kk * 4] = *(const float4*)&g_xc[bs[n] * 64 + kk * 4];
    }

    int o    = tid & 15;
    int slot = (tid >> 4) & 3;
    int g    = tid >> 6;          // warp-uniform group
    int c    = g * 16 + o;

    float w[48];
#pragma unroll
    for (int k = 0; k < 48; k++)
        w[k] = __ldg(&Wv[g * 768 + k * 16 + o]);
    float bvc = __ldg(&bv[c]);
    float sgn = (__ldg(&gamma[c]) >= 0.f) ? 1.f : -1.f;   // sign fold
    __syncthreads();

    for (int n = slot; n < NPB; n += 4) {
        if (node0 + n >= NN) break;
        const float* X = &xs[n * XS];
        const float* Y = &ys[n * XS];
        float u = 0.f, v = 0.f;
        if (g == 0) {
#pragma unroll
            for (int kk = 0; kk < 12; kk++) {
                float4 xv = *(const float4*)&X[kk * 4];
                FMA4(u, kk * 4, xv);
            }
        } else if (g == 1) {
#pragma unroll
            for (int kk = 0; kk < 4; kk++) {
                float4 xv = *(const float4*)&X[48 + kk * 4];
                FMA4(u, kk * 4, xv);
            }
#pragma unroll
            for (int kk = 0; kk < 8; kk++) {
                float4 xv = *(const float4*)&X[kk * 4];
                FMA4N(u, v, 16 + kk * 4, xv);
            }
        } else if (g == 2) {
#pragma unroll
            for (int kk = 0; kk < 8; kk++) {
                float4 xv = *(const float4*)&X[32 + kk * 4];
                FMA4N(u, v, kk * 4, xv);
            }
#pragma unroll
            for (int kk = 0; kk < 4; kk++) {
                float4 yv = *(const float4*)&Y[kk * 4];
                FMA4(v, 32 + kk * 4, yv);
            }
        } else {
#pragma unroll
            for (int kk = 0; kk < 12; kk++) {
                float4 yv = *(const float4*)&Y[16 + kk * 4];
                FMA4(v, kk * 4, yv);
            }
        }
        int base = (node0 + n) * 64 + c;
        g_u[base]  = sgn * (u + bvc);
        g_vw[base] = sgn * v;
    }
}

// ---------------- K3: warp-per-node signed-max + vsum + node-level BN stats ----------------
// Per-edge work: fmax + add per channel only. 8 edges in flight per iteration.
#define ACC2(v) \
    mx.x = fmaxf(mx.x, (v).x); mx.y = fmaxf(mx.y, (v).y); \
    vs.x += (v).x; vs.y += (v).y;

__global__ __launch_bounds__(256) void k_max() {
    __shared__ float ssum[64], ssq[64];
    int tid = threadIdx.x;
    if (tid < 64) { ssum[tid] = 0.f; ssq[tid] = 0.f; }
    __syncthreads();

    int lane = tid & 31;
    int c2   = lane * 2;                        // this lane's channel pair
    const char* vwb = (const char*)g_vw + lane * 8;   // per-lane gather base
    int wid  = (blockIdx.x * blockDim.x + tid) >> 5;
    int nw   = (gridDim.x * blockDim.x) >> 5;

    float2 s = make_float2(0.f, 0.f);
    float2 q = make_float2(0.f, 0.f);

    for (int node = wid; node < NN; node += nw) {
        int cnt  = g_cursor[node];
        int outd = g_outdeg[node];
        if ((cnt | outd) == 0) continue;

        float2 mx = make_float2(-FLT_MAX, -FLT_MAX);
        float2 vs = make_float2(0.f, 0.f);

        int m = cnt < CAP ? cnt : CAP;
        const int* bk = &g_bucket[node * CAP];
        int t = 0;
        for (; t + 8 <= m; t += 8) {            // 2 idx loads + 8 row gathers in flight
            int4 a4 = __ldg((const int4*)&bk[t]);
            int4 b4 = __ldg((const int4*)&bk[t + 4]);
            float2 v0 = __ldg((const float2*)(vwb + a4.x));
            float2 v1 = __ldg((const float2*)(vwb + a4.y));
            float2 v2 = __ldg((const float2*)(vwb + a4.z));
            float2 v3 = __ldg((const float2*)(vwb + a4.w));
            float2 v4 = __ldg((const float2*)(vwb + b4.x));
            float2 v5 = __ldg((const float2*)(vwb + b4.y));
            float2 v6 = __ldg((const float2*)(vwb + b4.z));
            float2 v7 = __ldg((const float2*)(vwb + b4.w));
            ACC2(v0); ACC2(v1); ACC2(v2); ACC2(v3);
            ACC2(v4); ACC2(v5); ACC2(v6); ACC2(v7);
        }
        for (; t + 4 <= m; t += 4) {
            int4 a4 = __ldg((const int4*)&bk[t]);
            float2 v0 = __ldg((const float2*)(vwb + a4.x));
            float2 v1 = __ldg((const float2*)(vwb + a4.y));
            float2 v2 = __ldg((const float2*)(vwb + a4.z));
            float2 v3 = __ldg((const float2*)(vwb + a4.w));
            ACC2(v0); ACC2(v1); ACC2(v2); ACC2(v3);
        }
        for (; t < m; t++) {
            int o = __ldg(&bk[t]);
            float2 v = __ldg((const float2*)(vwb + o));
            ACC2(v);
        }

        // node epilogue: store u'+mx' (fused for k_out), accumulate separable BN stats
        int rb = node * 64 + c2;
        float2 u  = *(const float2*)&g_u[rb];
        float2 vw = *(const float2*)&g_vw[rb];
        *(float2*)&g_mx[rb] = make_float2(u.x + mx.x, u.y + mx.y);
        float cf = (float)cnt, of = (float)outd;
        s.x += cf * u.x + of * vw.x;
        s.y += cf * u.y + of * vw.y;
        q.x += 2.f * u.x * vs.x + cf * u.x * u.x + of * vw.x * vw.x;
        q.y += 2.f * u.y * vs.y + cf * u.y * u.y + of * vw.y * vw.y;
    }
    atomicAdd(&ssum[c2 + 0], s.x);
    atomicAdd(&ssum[c2 + 1], s.y);
    atomicAdd(&ssq[c2 + 0], q.x);
    atomicAdd(&ssq[c2 + 1], q.y);
    __syncthreads();
    if (tid < 64) {
        atomicAdd(&g_sum[tid],   ssum[tid]);
        atomicAdd(&g_sumsq[tid], ssq[tid]);
    }
}

// ---------------- K4: per-node output, BN affine computed per block (sign-aware) ----------------
// out[i,c] = deg>0 ? relu(a'_c * (u'+mx')[i,c] + shift_c) : 0
__global__ __launch_bounds__(256) void k_out(const float* __restrict__ gamma,
                                             const float* __restrict__ beta,
                                             float* __restrict__ out) {
    __shared__ float sc[64], sh[64];
    int tid = threadIdx.x;
    if (tid < 64) {
        float gm  = gamma[tid];
        float sg  = (gm >= 0.f) ? 1.f : -1.f;
        float invE = 1.f / (float)EE;
        float mu  = sg * g_sum[tid] * invE;                 // un-sign the mean
        float var = fmaxf(g_sumsq[tid] * invE - mu * mu, 0.f);
        float a   = gm * rsqrtf(var + BN_EPS);
        sc[tid] = a * sg;                                   // a' = |gamma|*rsqrt (acts on signed u'+mx')
        sh[tid] = beta[tid] - a * mu;
    }
    __syncthreads();

    int idx  = blockIdx.x * blockDim.x + tid;   // NN*16 threads
    int node = idx >> 4;
    int c4   = idx & 15;
    int deg  = g_cursor[node];
    float4 r = make_float4(0.f, 0.f, 0.f, 0.f);
    if (deg > 0) {
        float4 a  = *(const float4*)&sc[c4 * 4];
        float4 b  = *(const float4*)&sh[c4 * 4];
        float4 t  = *(const float4*)&g_mx[node * 64 + c4 * 4];   // u'+mx' fused
        r.x = fmaxf(fmaf(a.x, t.x, b.x), 0.f);
        r.y = fmaxf(fmaf(a.y, t.y, b.y), 0.f);
        r.z = fmaxf(fmaf(a.z, t.z, b.z), 0.f);
        r.w = fmaxf(fmaf(a.w, t.w, b.w), 0.f);
    }
    *(float4*)&out[node * 64 + c4 * 4] = r;
}

// ---------------- launch ----------------
extern "C" void kernel_launch(void* const* d_in, const int* in_sizes, int n_in,
                              void* d_out, int out_size) {
    const float* x        = (const float*)d_in[0];
    const int*   batch    = (const int*)  d_in[1];
    const int*   ei       = (const int*)  d_in[2];
    const float* x_center = (const float*)d_in[3];
    // d_in[4] = batch_center (unused by reference)
    const float* W_c      = (const float*)d_in[5];
    const float* b_c      = (const float*)d_in[6];
    const float* W_v      = (const float*)d_in[7];
    const float* b_v      = (const float*)d_in[8];
    const float* gamma    = (const float*)d_in[9];
    const float* beta     = (const float*)d_in[10];
    float* out = (float*)d_out;

    k_centroid<<<250, 256>>>(x_center, W_c, b_c);              // also zeroes counters
    k_nodes   <<<(NN + NPB - 1) / NPB, 256>>>(x, batch, W_v, b_v, gamma, ei);  // + fused bucketing
    k_max     <<<1184, 256>>>();                               // single wave: 8 blocks x 148 SMs
    k_out     <<<NN * 16 / 256, 256>>>(gamma, beta, out);
}